// round 7
// baseline (speedup 1.0000x reference)
#include <cuda_runtime.h>
#include <cuda_bf16.h>
#include <math.h>
#include <stdint.h>

#define D_MODEL 1024
#define NHEADS  16
#define DK      64
#define SEQ     2048
#define BATCH   2
#define NTOK    (BATCH*SEQ)   // 4096
#define DFF     4096

// ---------------- scratch (no allocations allowed) ----------------
__device__ float g_ctx[NTOK*D_MODEL];
__device__ float g_s1 [NTOK*D_MODEL];
__device__ float g_x1 [NTOK*D_MODEL];
__device__ float g_ff [NTOK*DFF];
__device__ float g_s2 [NTOK*D_MODEL];

// q/k/v in [3][B,H,S,DK] as pre-split bf16 hi/lo (q pre-scaled by 1/8)
__device__ __nv_bfloat16 g_qkvh[3*NTOK*D_MODEL];
__device__ __nv_bfloat16 g_qkvl[3*NTOK*D_MODEL];

// pre-split transposed weights [N][K], bf16 hi/lo
__device__ __nv_bfloat16 g_wqkv_hi[3*D_MODEL*D_MODEL];
__device__ __nv_bfloat16 g_wqkv_lo[3*D_MODEL*D_MODEL];
__device__ __nv_bfloat16 g_wo_hi  [D_MODEL*D_MODEL];
__device__ __nv_bfloat16 g_wo_lo  [D_MODEL*D_MODEL];
__device__ __nv_bfloat16 g_w1_hi  [DFF*D_MODEL];
__device__ __nv_bfloat16 g_w1_lo  [DFF*D_MODEL];
__device__ __nv_bfloat16 g_w2_hi  [D_MODEL*DFF];
__device__ __nv_bfloat16 g_w2_lo  [D_MODEL*DFF];

// ---------------- helpers ----------------
__device__ __forceinline__ uint32_t smem_u32(const void* p) {
    uint32_t a;
    asm("{ .reg .u64 t; cvta.to.shared.u64 t, %1; cvt.u32.u64 %0, t; }" : "=r"(a) : "l"(p));
    return a;
}
__device__ __forceinline__ void ldsm4(uint32_t* r, uint32_t addr) {
    asm volatile("ldmatrix.sync.aligned.m8n8.x4.shared.b16 {%0,%1,%2,%3}, [%4];"
        : "=r"(r[0]), "=r"(r[1]), "=r"(r[2]), "=r"(r[3]) : "r"(addr));
}
__device__ __forceinline__ void ldsm4t(uint32_t* r, uint32_t addr) {
    asm volatile("ldmatrix.sync.aligned.m8n8.x4.trans.shared.b16 {%0,%1,%2,%3}, [%4];"
        : "=r"(r[0]), "=r"(r[1]), "=r"(r[2]), "=r"(r[3]) : "r"(addr));
}
__device__ __forceinline__ void mma_bf16(float* d, const uint32_t* a, const uint32_t* b) {
    asm volatile(
        "mma.sync.aligned.m16n8k16.row.col.f32.bf16.bf16.f32 "
        "{%0,%1,%2,%3}, {%4,%5,%6,%7}, {%8,%9}, {%0,%1,%2,%3};"
        : "+f"(d[0]), "+f"(d[1]), "+f"(d[2]), "+f"(d[3])
        : "r"(a[0]), "r"(a[1]), "r"(a[2]), "r"(a[3]), "r"(b[0]), "r"(b[1]));
}
__device__ __forceinline__ uint32_t packbf2(float x, float y) {
    __nv_bfloat162 h = __floats2bfloat162_rn(x, y);
    return *(uint32_t*)&h;
}
__device__ __forceinline__ uint32_t packbf16pair(__nv_bfloat16 a, __nv_bfloat16 b) {
    return (uint32_t)__bfloat16_as_ushort(a) | ((uint32_t)__bfloat16_as_ushort(b) << 16);
}

// ---------------- weight prep: W[K][N] fp32 -> T[N][K] bf16 hi/lo ----------------
__global__ void prep_w(const float* __restrict__ W, __nv_bfloat16* __restrict__ Thi,
                       __nv_bfloat16* __restrict__ Tlo, int K, int N)
{
    __shared__ float t[32][33];
    const int k0 = blockIdx.y * 32, n0 = blockIdx.x * 32;
    const int tx = threadIdx.x, ty = threadIdx.y;   // 32 x 8
#pragma unroll
    for (int r = 0; r < 4; r++)
        t[ty + 8*r][tx] = W[(size_t)(k0 + ty + 8*r) * N + n0 + tx];
    __syncthreads();
#pragma unroll
    for (int r = 0; r < 4; r++) {
        const int n = n0 + ty + 8*r, k = k0 + tx;
        float x = t[tx][ty + 8*r];
        __nv_bfloat16 hi = __float2bfloat16(x);
        __nv_bfloat16 lo = __float2bfloat16(x - __bfloat162float(hi));
        Thi[(size_t)n * K + k] = hi;
        Tlo[(size_t)n * K + k] = lo;
    }
}

// ---------------- bf16x3 mma.sync GEMM ----------------
#define GS_BUF   40960
#define GS_AH    0
#define GS_AL    10240
#define GS_BH    20480
#define GS_BL    30720
#define SMEM_G   (2*GS_BUF)

template<int EPI>
__global__ __launch_bounds__(256, 1)
void bf16_gemm(const float* __restrict__ A,
               const __nv_bfloat16* __restrict__ Bhi, const __nv_bfloat16* __restrict__ Blo,
               float* __restrict__ C, const float* __restrict__ bias,
               const float* __restrict__ res, int N, int K,
               __nv_bfloat16* __restrict__ Ohi, __nv_bfloat16* __restrict__ Olo)
{
    extern __shared__ char smem[];
    const uint32_t sbase = smem_u32(smem);
    const int tid = threadIdx.x, wid = tid >> 5, lane = tid & 31;
    const int g = lane >> 2, t = lane & 3;
    const int wm = wid >> 2, wn = wid & 3;
    const int bm = blockIdx.y, bn = blockIdx.x;

    float c[4][4][4];
#pragma unroll
    for (int mt = 0; mt < 4; mt++)
#pragma unroll
        for (int nt = 0; nt < 4; nt++)
#pragma unroll
            for (int f = 0; f < 4; f++) c[mt][nt][f] = 0.f;

    const int arow = tid >> 1, ahalf = tid & 1;
    const float* gA = A + (size_t)(bm * 128 + arow) * K + ahalf * 16;

    auto cp_B = [&](int buf, int kb) {
#pragma unroll
        for (int j = 0; j < 4; j++) {
            const int cidx = tid + 256 * j;
            const int isLo = cidx >> 9;
            const int row  = (cidx >> 2) & 127;
            const int kc   = cidx & 3;
            const __nv_bfloat16* src = (isLo ? Blo : Bhi)
                + (size_t)(bn * 128 + row) * K + kb * 32 + kc * 8;
            const uint32_t dst = sbase + buf * GS_BUF + (isLo ? GS_BL : GS_BH)
                + row * 80 + kc * 16;
            asm volatile("cp.async.cg.shared.global [%0], [%1], 16;\n" :: "r"(dst), "l"(src));
        }
        asm volatile("cp.async.commit_group;\n");
    };

    float4 areg[4];
    auto load_A = [&](int kb) {
        const float* p = gA + kb * 32;
#pragma unroll
        for (int i = 0; i < 4; i++) areg[i] = *(const float4*)(p + 4 * i);
    };
    auto store_A = [&](int buf) {
        char* base = smem + buf * GS_BUF;
        const int off = arow * 80 + ahalf * 32;
        uint32_t* ph = (uint32_t*)(base + GS_AH + off);
        uint32_t* pl = (uint32_t*)(base + GS_AL + off);
#pragma unroll
        for (int i = 0; i < 4; i++) {
            float f0 = areg[i].x, f1 = areg[i].y, f2 = areg[i].z, f3 = areg[i].w;
            __nv_bfloat16 h0 = __float2bfloat16(f0), h1 = __float2bfloat16(f1);
            __nv_bfloat16 h2 = __float2bfloat16(f2), h3 = __float2bfloat16(f3);
            float l0 = f0 - __bfloat162float(h0), l1 = f1 - __bfloat162float(h1);
            float l2 = f2 - __bfloat162float(h2), l3 = f3 - __bfloat162float(h3);
            ph[2*i]   = packbf16pair(h0, h1);
            ph[2*i+1] = packbf16pair(h2, h3);
            pl[2*i]   = packbf2(l0, l1);
            pl[2*i+1] = packbf2(l2, l3);
        }
    };

    const uint32_t a_off = (uint32_t)((wm * 64 + (lane & 15)) * 80 + ((lane >> 4) << 4));
    const uint32_t b_off = (uint32_t)((wn * 32 + ((lane >> 4) << 3) + (lane & 7)) * 80
                                      + (((lane >> 3) & 1) << 4));

    const int niter = K >> 5;
    load_A(0);
    cp_B(0, 0);
    store_A(0);
    asm volatile("cp.async.wait_group 0;\n");
    __syncthreads();

    for (int it = 0; it < niter; it++) {
        const int buf = it & 1;
        if (it + 1 < niter) { load_A(it + 1); cp_B(buf ^ 1, it + 1); }

        const uint32_t sb = sbase + buf * GS_BUF;
#pragma unroll
        for (int ks = 0; ks < 2; ks++) {
            uint32_t Ah[4][4], Al[4][4], Bh[2][4], Bl[2][4];
#pragma unroll
            for (int mt = 0; mt < 4; mt++) {
                const uint32_t aa = sb + a_off + mt * (16 * 80) + ks * 32;
                ldsm4(Ah[mt], aa + GS_AH);
                ldsm4(Al[mt], aa + GS_AL);
            }
#pragma unroll
            for (int ng = 0; ng < 2; ng++) {
                const uint32_t ba = sb + b_off + ng * (16 * 80) + ks * 32;
                ldsm4(Bh[ng], ba + GS_BH);
                ldsm4(Bl[ng], ba + GS_BL);
            }
#pragma unroll
            for (int mt = 0; mt < 4; mt++)
#pragma unroll
                for (int nt = 0; nt < 4; nt++) {
                    const uint32_t* bh = &Bh[nt >> 1][(nt & 1) * 2];
                    const uint32_t* bl = &Bl[nt >> 1][(nt & 1) * 2];
                    mma_bf16(c[mt][nt], Ah[mt], bh);
                    mma_bf16(c[mt][nt], Ah[mt], bl);
                    mma_bf16(c[mt][nt], Al[mt], bh);
                }
        }

        if (it + 1 < niter) {
            store_A(buf ^ 1);
            asm volatile("cp.async.wait_group 0;\n");
        }
        __syncthreads();
    }

    // ---------------- epilogue ----------------
#pragma unroll
    for (int mt = 0; mt < 4; mt++) {
        const int r0 = bm * 128 + wm * 64 + mt * 16 + g;
#pragma unroll
        for (int nt = 0; nt < 4; nt++) {
            const int c0 = bn * 128 + wn * 32 + nt * 8 + t * 2;
#pragma unroll
            for (int half = 0; half < 2; half++) {
                const int r = r0 + half * 8;
                if (EPI == 1) {
                    float v0 = c[mt][nt][half * 2], v1 = c[mt][nt][half * 2 + 1];
                    const int which = c0 >> 10, cm = c0 & 1023;
                    if (which == 0) { v0 *= 0.125f; v1 *= 0.125f; }
                    __nv_bfloat16 h0 = __float2bfloat16(v0), h1 = __float2bfloat16(v1);
                    __nv_bfloat16 l0 = __float2bfloat16(v0 - __bfloat162float(h0));
                    __nv_bfloat16 l1 = __float2bfloat16(v1 - __bfloat162float(h1));
                    const size_t idx = (size_t)which * (NTOK * D_MODEL)
                        + (((size_t)((r >> 11) * NHEADS + (cm >> 6)) * SEQ + (r & 2047)) * DK + (cm & 63));
                    *(uint32_t*)(Ohi + idx) = packbf16pair(h0, h1);
                    *(uint32_t*)(Olo + idx) = packbf16pair(l0, l1);
                } else {
#pragma unroll
                    for (int e = 0; e < 2; e++) {
                        const int cc = c0 + e;
                        const float vacc = c[mt][nt][half * 2 + e];
                        if (EPI == 2) {
                            C[(size_t)r * N + cc] = vacc + bias[cc] + res[(size_t)r * N + cc];
                        } else {
                            float v = vacc + bias[cc];
                            C[(size_t)r * N + cc] = v > 0.f ? v : 0.f;
                        }
                    }
                }
            }
        }
    }
}

// ---------------- tensor-core flash attention ----------------
// Per block: 64 queries x one head. 256 threads (8 warps: 2m x 4n).
// smem byte offsets (row stride 144B for bf16 tiles, 288B for fp32 S):
#define ATQ_H 0
#define ATQ_L 9216
#define ATK_H 18432
#define ATK_L 27648
#define ATV_H 36864
#define ATV_L 46080
#define ATS   55296
#define ATP_H 73728
#define ATP_L 82944
#define ATFB  92160
#define ATLB  92416
#define ATSMEM 92672

__global__ __launch_bounds__(256)
void attn_mma(const __nv_bfloat16* __restrict__ qkvh, const __nv_bfloat16* __restrict__ qkvl,
              const int* __restrict__ mask, float* __restrict__ ctx)
{
    extern __shared__ char sm[];
    const uint32_t sb = smem_u32(sm);
    const int tid = threadIdx.x, wid = tid >> 5, lane = tid & 31;
    const int g = lane >> 2, t = lane & 3;
    const int wm = wid >> 2, wn = wid & 3;
    const int qb = blockIdx.x, h = blockIdx.y, b = blockIdx.z;
    const size_t hoff = ((size_t)(b * NHEADS + h)) * SEQ * DK;

    const __nv_bfloat16* qh = qkvh + hoff + (size_t)qb * 64 * DK;
    const __nv_bfloat16* ql = qkvl + hoff + (size_t)qb * 64 * DK;
    const __nv_bfloat16* kh = qkvh + (size_t)NTOK * D_MODEL + hoff;
    const __nv_bfloat16* kl = qkvl + (size_t)NTOK * D_MODEL + hoff;
    const __nv_bfloat16* vh = qkvh + (size_t)2 * NTOK * D_MODEL + hoff;
    const __nv_bfloat16* vl = qkvl + (size_t)2 * NTOK * D_MODEL + hoff;

    // load Q hi/lo (arr uniform per j)
#pragma unroll
    for (int j = 0; j < 4; j++) {
        const int cidx = tid + j * 256;
        const int arr = cidx >> 9, cc = cidx & 511;
        const int row = cc >> 3, k8 = cc & 7;
        const __nv_bfloat16* src = (arr == 0 ? qh : ql) + row * DK + k8 * 8;
        *(uint4*)(sm + ATQ_H + arr * 9216 + row * 144 + k8 * 16) = *(const uint4*)src;
    }

    const int srow = tid >> 2, ssub = tid & 3;
    float m_ = -1e30f, l_ = 0.f;
    float co[2][2][4];
#pragma unroll
    for (int mt = 0; mt < 2; mt++)
#pragma unroll
        for (int nt = 0; nt < 2; nt++)
#pragma unroll
            for (int f = 0; f < 4; f++) co[mt][nt][f] = 0.f;

    const uint32_t qa_off = (uint32_t)((wm * 32 + (lane & 15)) * 144 + ((lane >> 4) << 4));
    const uint32_t kb_off = (uint32_t)((wn * 16 + ((lane >> 4) << 3) + (lane & 7)) * 144
                                       + (((lane >> 3) & 1) << 4));
    const uint32_t vb_off = (uint32_t)(((((lane >> 3) & 1) << 3) + (lane & 7)) * 144
                                       + ((lane >> 4) << 4) + wn * 32);

    for (int kv0 = 0; kv0 < SEQ; kv0 += 64) {
        // load K/V hi/lo (arr uniform per j)
#pragma unroll
        for (int j = 0; j < 8; j++) {
            const int cidx = tid + j * 256;
            const int arr = cidx >> 9, cc = cidx & 511;
            const int row = cc >> 3, k8 = cc & 7;
            const __nv_bfloat16* src =
                (arr == 0 ? kh : arr == 1 ? kl : arr == 2 ? vh : vl)
                + (size_t)(kv0 + row) * DK + k8 * 8;
            *(uint4*)(sm + ATK_H + arr * 9216 + row * 144 + k8 * 16) = *(const uint4*)src;
        }
        __syncthreads();

        // ---- S = Q K^T (bf16x3) ----
        float cs[2][2][4];
#pragma unroll
        for (int mt = 0; mt < 2; mt++)
#pragma unroll
            for (int nt = 0; nt < 2; nt++)
#pragma unroll
                for (int f = 0; f < 4; f++) cs[mt][nt][f] = 0.f;
#pragma unroll
        for (int ks = 0; ks < 4; ks++) {
            uint32_t Qh_[2][4], Ql_[2][4], Kh_[4], Kl_[4];
#pragma unroll
            for (int mt = 0; mt < 2; mt++) {
                const uint32_t aa = sb + qa_off + mt * (16 * 144) + ks * 32;
                ldsm4(Qh_[mt], aa + ATQ_H);
                ldsm4(Ql_[mt], aa + ATQ_L);
            }
            const uint32_t ba = sb + kb_off + ks * 32;
            ldsm4(Kh_, ba + ATK_H);
            ldsm4(Kl_, ba + ATK_L);
#pragma unroll
            for (int mt = 0; mt < 2; mt++)
#pragma unroll
                for (int nt = 0; nt < 2; nt++) {
                    const uint32_t* bh = &Kh_[nt * 2];
                    const uint32_t* bl = &Kl_[nt * 2];
                    mma_bf16(cs[mt][nt], Qh_[mt], bh);
                    mma_bf16(cs[mt][nt], Qh_[mt], bl);
                    mma_bf16(cs[mt][nt], Ql_[mt], bh);
                }
        }
        // store S fragments to smem (fp32)
#pragma unroll
        for (int mt = 0; mt < 2; mt++) {
            const int r0 = wm * 32 + mt * 16 + g;
#pragma unroll
            for (int nt = 0; nt < 2; nt++) {
                const int col = wn * 16 + nt * 8 + t * 2;
                *(float2*)(sm + ATS + r0 * 288 + col * 4) =
                    make_float2(cs[mt][nt][0], cs[mt][nt][1]);
                *(float2*)(sm + ATS + (r0 + 8) * 288 + col * 4) =
                    make_float2(cs[mt][nt][2], cs[mt][nt][3]);
            }
        }
        __syncthreads();

        // ---- online softmax: row = tid>>2, 16 kv per thread ----
        {
            float p[16];
            const float* srp = (const float*)(sm + ATS + srow * 288) + ssub * 16;
#pragma unroll
            for (int q4 = 0; q4 < 4; q4++) {
                float4 v = *(const float4*)(srp + q4 * 4);
                p[4*q4+0] = v.x; p[4*q4+1] = v.y; p[4*q4+2] = v.z; p[4*q4+3] = v.w;
            }
            const int4* mp = (const int4*)(mask + b * SEQ + kv0 + ssub * 16);
#pragma unroll
            for (int q4 = 0; q4 < 4; q4++) {
                int4 mv = mp[q4];
                if (mv.x == 0) p[4*q4+0] = -1e9f;
                if (mv.y == 0) p[4*q4+1] = -1e9f;
                if (mv.z == 0) p[4*q4+2] = -1e9f;
                if (mv.w == 0) p[4*q4+3] = -1e9f;
            }
            float tmax = p[0];
#pragma unroll
            for (int i = 1; i < 16; i++) tmax = fmaxf(tmax, p[i]);
            tmax = fmaxf(tmax, __shfl_xor_sync(0xffffffffu, tmax, 1, 4));
            tmax = fmaxf(tmax, __shfl_xor_sync(0xffffffffu, tmax, 2, 4));
            const float mn = fmaxf(m_, tmax);
            float rs = 0.f;
#pragma unroll
            for (int i = 0; i < 16; i++) { p[i] = __expf(p[i] - mn); rs += p[i]; }
            rs += __shfl_xor_sync(0xffffffffu, rs, 1, 4);
            rs += __shfl_xor_sync(0xffffffffu, rs, 2, 4);
            const float f = __expf(m_ - mn);
            l_ = l_ * f + rs;
            m_ = mn;
            // write P hi/lo bf16
            uint32_t hp[8], lp[8];
#pragma unroll
            for (int i = 0; i < 8; i++) {
                __nv_bfloat16 h0 = __float2bfloat16(p[2*i]), h1 = __float2bfloat16(p[2*i+1]);
                float l0 = p[2*i] - __bfloat162float(h0), l1 = p[2*i+1] - __bfloat162float(h1);
                hp[i] = packbf16pair(h0, h1);
                lp[i] = packbf2(l0, l1);
            }
            uint4* dph = (uint4*)(sm + ATP_H + srow * 144 + ssub * 32);
            uint4* dpl = (uint4*)(sm + ATP_L + srow * 144 + ssub * 32);
            dph[0] = make_uint4(hp[0], hp[1], hp[2], hp[3]);
            dph[1] = make_uint4(hp[4], hp[5], hp[6], hp[7]);
            dpl[0] = make_uint4(lp[0], lp[1], lp[2], lp[3]);
            dpl[1] = make_uint4(lp[4], lp[5], lp[6], lp[7]);
            if (ssub == 0) ((float*)(sm + ATFB))[srow] = f;
        }
        __syncthreads();

        // ---- rescale O, then O += P V (bf16x3) ----
        {
            const float* fb = (const float*)(sm + ATFB);
            const float f00 = fb[wm * 32 + g],      f01 = fb[wm * 32 + 8 + g];
            const float f10 = fb[wm * 32 + 16 + g], f11 = fb[wm * 32 + 24 + g];
#pragma unroll
            for (int nt = 0; nt < 2; nt++) {
                co[0][nt][0] *= f00; co[0][nt][1] *= f00;
                co[0][nt][2] *= f01; co[0][nt][3] *= f01;
                co[1][nt][0] *= f10; co[1][nt][1] *= f10;
                co[1][nt][2] *= f11; co[1][nt][3] *= f11;
            }
        }
#pragma unroll
        for (int ks = 0; ks < 4; ks++) {
            uint32_t Ph_[2][4], Pl_[2][4], Vh_[4], Vl_[4];
#pragma unroll
            for (int mt = 0; mt < 2; mt++) {
                const uint32_t aa = sb + qa_off + mt * (16 * 144) + ks * 32;
                ldsm4(Ph_[mt], aa + ATP_H);
                ldsm4(Pl_[mt], aa + ATP_L);
            }
            const uint32_t ba = sb + vb_off + ks * (16 * 144);
            ldsm4t(Vh_, ba + ATV_H);
            ldsm4t(Vl_, ba + ATV_L);
#pragma unroll
            for (int mt = 0; mt < 2; mt++)
#pragma unroll
                for (int nt = 0; nt < 2; nt++) {
                    const uint32_t* bh = &Vh_[nt * 2];
                    const uint32_t* bl = &Vl_[nt * 2];
                    mma_bf16(co[mt][nt], Ph_[mt], bh);
                    mma_bf16(co[mt][nt], Ph_[mt], bl);
                    mma_bf16(co[mt][nt], Pl_[mt], bh);
                }
        }
        __syncthreads();
    }

    if (ssub == 0) ((float*)(sm + ATLB))[srow] = l_;
    __syncthreads();
    const float* lb = (const float*)(sm + ATLB);

#pragma unroll
    for (int mt = 0; mt < 2; mt++) {
#pragma unroll
        for (int half = 0; half < 2; half++) {
            const int row = wm * 32 + mt * 16 + g + half * 8;
            const float inv = 1.0f / lb[row];
            float* dst = ctx + ((size_t)(b * SEQ + qb * 64 + row)) * D_MODEL + h * 64;
#pragma unroll
            for (int nt = 0; nt < 2; nt++) {
                const int col = wn * 16 + nt * 8 + t * 2;
                *(float2*)(dst + col) = make_float2(co[mt][nt][half * 2] * inv,
                                                    co[mt][nt][half * 2 + 1] * inv);
            }
        }
    }
}

// ---------------- LayerNorm (ddof=1, eps added to std) ----------------
__device__ __forceinline__ float warp_sum(float s) {
#pragma unroll
    for (int off = 16; off; off >>= 1) s += __shfl_xor_sync(0xffffffffu, s, off);
    return s;
}

__global__ __launch_bounds__(256)
void ln_kernel(const float* __restrict__ in, const float* __restrict__ alpha,
               const float* __restrict__ beta, float* __restrict__ out)
{
    __shared__ float red[8];
    const int row = blockIdx.x, tid = threadIdx.x;
    const float* rp = in + (size_t)row * D_MODEL;
    float4 v = *(const float4*)(rp + tid*4);

    float s = v.x + v.y + v.z + v.w;
    s = warp_sum(s);
    if ((tid & 31) == 0) red[tid >> 5] = s;
    __syncthreads();
    float tot = 0.f;
#pragma unroll
    for (int i = 0; i < 8; i++) tot += red[i];
    float mean = tot * (1.0f / 1024.0f);

    float dx = v.x - mean, dy = v.y - mean, dz = v.z - mean, dw = v.w - mean;
    float sq = dx*dx + dy*dy + dz*dz + dw*dw;
    __syncthreads();
    sq = warp_sum(sq);
    if ((tid & 31) == 0) red[tid >> 5] = sq;
    __syncthreads();
    float tot2 = 0.f;
#pragma unroll
    for (int i = 0; i < 8; i++) tot2 += red[i];
    float var  = tot2 * (1.0f / 1023.0f);
    float rstd = 1.0f / (sqrtf(var) + 1e-6f);

    float4 a = *(const float4*)(alpha + tid*4);
    float4 bb = *(const float4*)(beta + tid*4);
    float4 o;
    o.x = a.x * dx * rstd + bb.x;
    o.y = a.y * dy * rstd + bb.y;
    o.z = a.z * dz * rstd + bb.z;
    o.w = a.w * dw * rstd + bb.w;
    *(float4*)(out + (size_t)row * D_MODEL + tid*4) = o;
}

// ---------------- host ----------------
extern "C" void kernel_launch(void* const* d_in, const int* in_sizes, int n_in,
                              void* d_out, int out_size)
{
    const float* x      = (const float*)d_in[0];
    const int*   mask   = (const int*)  d_in[1];
    const float* wq     = (const float*)d_in[2];
    const float* wk     = (const float*)d_in[3];
    const float* wv     = (const float*)d_in[4];
    const float* wo     = (const float*)d_in[5];
    const float* wo_b   = (const float*)d_in[6];
    const float* w1     = (const float*)d_in[7];
    const float* b1     = (const float*)d_in[8];
    const float* w2     = (const float*)d_in[9];
    const float* b2     = (const float*)d_in[10];
    const float* alpha1 = (const float*)d_in[11];
    const float* bias1  = (const float*)d_in[12];
    const float* alpha2 = (const float*)d_in[13];
    const float* bias2  = (const float*)d_in[14];
    float* out = (float*)d_out;

    float *ctx, *s1, *x1, *ff, *s2;
    __nv_bfloat16 *qkvh, *qkvl;
    __nv_bfloat16 *wqkv_hi, *wqkv_lo, *wo_hi, *wo_lo, *w1_hi, *w1_lo, *w2_hi, *w2_lo;
    cudaGetSymbolAddress((void**)&ctx, g_ctx);
    cudaGetSymbolAddress((void**)&s1,  g_s1);
    cudaGetSymbolAddress((void**)&x1,  g_x1);
    cudaGetSymbolAddress((void**)&ff,  g_ff);
    cudaGetSymbolAddress((void**)&s2,  g_s2);
    cudaGetSymbolAddress((void**)&qkvh, g_qkvh);
    cudaGetSymbolAddress((void**)&qkvl, g_qkvl);
    cudaGetSymbolAddress((void**)&wqkv_hi, g_wqkv_hi);
    cudaGetSymbolAddress((void**)&wqkv_lo, g_wqkv_lo);
    cudaGetSymbolAddress((void**)&wo_hi, g_wo_hi);
    cudaGetSymbolAddress((void**)&wo_lo, g_wo_lo);
    cudaGetSymbolAddress((void**)&w1_hi, g_w1_hi);
    cudaGetSymbolAddress((void**)&w1_lo, g_w1_lo);
    cudaGetSymbolAddress((void**)&w2_hi, g_w2_hi);
    cudaGetSymbolAddress((void**)&w2_lo, g_w2_lo);

    // idempotent; no static guards allowed
    cudaFuncSetAttribute(bf16_gemm<1>, cudaFuncAttributeMaxDynamicSharedMemorySize, SMEM_G);
    cudaFuncSetAttribute(bf16_gemm<2>, cudaFuncAttributeMaxDynamicSharedMemorySize, SMEM_G);
    cudaFuncSetAttribute(bf16_gemm<3>, cudaFuncAttributeMaxDynamicSharedMemorySize, SMEM_G);
    cudaFuncSetAttribute(attn_mma,     cudaFuncAttributeMaxDynamicSharedMemorySize, ATSMEM);

    dim3 tblk(32, 8);
    prep_w<<<dim3(D_MODEL/32, D_MODEL/32), tblk>>>(wq, wqkv_hi,                     wqkv_lo,                     D_MODEL, D_MODEL);
    prep_w<<<dim3(D_MODEL/32, D_MODEL/32), tblk>>>(wk, wqkv_hi + D_MODEL*D_MODEL,   wqkv_lo + D_MODEL*D_MODEL,   D_MODEL, D_MODEL);
    prep_w<<<dim3(D_MODEL/32, D_MODEL/32), tblk>>>(wv, wqkv_hi + 2*D_MODEL*D_MODEL, wqkv_lo + 2*D_MODEL*D_MODEL, D_MODEL, D_MODEL);
    prep_w<<<dim3(D_MODEL/32, D_MODEL/32), tblk>>>(wo, wo_hi, wo_lo, D_MODEL, D_MODEL);
    prep_w<<<dim3(DFF/32,     D_MODEL/32), tblk>>>(w1, w1_hi, w1_lo, D_MODEL, DFF);
    prep_w<<<dim3(D_MODEL/32, DFF/32),     tblk>>>(w2, w2_hi, w2_lo, DFF, D_MODEL);

    // fused QKV projection (N=3072) -> bf16 hi/lo head-transposed, q pre-scaled
    bf16_gemm<1><<<dim3(24, 32), 256, SMEM_G>>>(x, wqkv_hi, wqkv_lo, nullptr, nullptr, nullptr,
                                                3*D_MODEL, D_MODEL, qkvh, qkvl);

    attn_mma<<<dim3(SEQ/64, NHEADS, BATCH), 256, ATSMEM>>>(qkvh, qkvl, mask, ctx);

    // O projection + residual, LN1
    bf16_gemm<2><<<dim3(8, 32), 256, SMEM_G>>>(ctx, wo_hi, wo_lo, s1, wo_b, x, D_MODEL, D_MODEL, nullptr, nullptr);
    ln_kernel<<<NTOK, 256>>>(s1, alpha1, bias1, x1);

    // FFN
    bf16_gemm<3><<<dim3(32, 32), 256, SMEM_G>>>(x1, w1_hi, w1_lo, ff, b1, nullptr, DFF, D_MODEL, nullptr, nullptr);
    bf16_gemm<2><<<dim3(8, 32), 256, SMEM_G>>>(ff, w2_hi, w2_lo, s2, b2, x1, D_MODEL, DFF, nullptr, nullptr);
    ln_kernel<<<NTOK, 256>>>(s2, alpha2, bias2, out);
}

// round 10
// speedup vs baseline: 1.6278x; 1.6278x over previous
#include <cuda_runtime.h>
#include <cuda_bf16.h>
#include <math.h>
#include <stdint.h>

#define D_MODEL 1024
#define NHEADS  16
#define DK      64
#define SEQ     2048
#define BATCH   2
#define NTOK    (BATCH*SEQ)   // 4096
#define DFF     4096

// ---------------- scratch (no allocations allowed) ----------------
__device__ float g_ctx[NTOK*D_MODEL];
__device__ float g_s1 [NTOK*D_MODEL];
__device__ float g_x1 [NTOK*D_MODEL];
__device__ float g_ff [NTOK*DFF];
__device__ float g_s2 [NTOK*D_MODEL];

// q/k/v in [3][B,H,S,DK] as pre-split bf16 hi/lo (q pre-scaled by 1/8)
__device__ __nv_bfloat16 g_qkvh[3*NTOK*D_MODEL];
__device__ __nv_bfloat16 g_qkvl[3*NTOK*D_MODEL];

// pre-split transposed weights [N][K], bf16 hi/lo
__device__ __nv_bfloat16 g_wqkv_hi[3*D_MODEL*D_MODEL];
__device__ __nv_bfloat16 g_wqkv_lo[3*D_MODEL*D_MODEL];
__device__ __nv_bfloat16 g_wo_hi  [D_MODEL*D_MODEL];
__device__ __nv_bfloat16 g_wo_lo  [D_MODEL*D_MODEL];
__device__ __nv_bfloat16 g_w1_hi  [DFF*D_MODEL];
__device__ __nv_bfloat16 g_w1_lo  [DFF*D_MODEL];
__device__ __nv_bfloat16 g_w2_hi  [D_MODEL*DFF];
__device__ __nv_bfloat16 g_w2_lo  [D_MODEL*DFF];

// ---------------- helpers ----------------
__device__ __forceinline__ uint32_t smem_u32(const void* p) {
    uint32_t a;
    asm("{ .reg .u64 t; cvta.to.shared.u64 t, %1; cvt.u32.u64 %0, t; }" : "=r"(a) : "l"(p));
    return a;
}
__device__ __forceinline__ void ldsm4(uint32_t* r, uint32_t addr) {
    asm volatile("ldmatrix.sync.aligned.m8n8.x4.shared.b16 {%0,%1,%2,%3}, [%4];"
        : "=r"(r[0]), "=r"(r[1]), "=r"(r[2]), "=r"(r[3]) : "r"(addr));
}
__device__ __forceinline__ void ldsm4t(uint32_t* r, uint32_t addr) {
    asm volatile("ldmatrix.sync.aligned.m8n8.x4.trans.shared.b16 {%0,%1,%2,%3}, [%4];"
        : "=r"(r[0]), "=r"(r[1]), "=r"(r[2]), "=r"(r[3]) : "r"(addr));
}
__device__ __forceinline__ void mma_bf16(float* d, const uint32_t* a, const uint32_t* b) {
    asm volatile(
        "mma.sync.aligned.m16n8k16.row.col.f32.bf16.bf16.f32 "
        "{%0,%1,%2,%3}, {%4,%5,%6,%7}, {%8,%9}, {%0,%1,%2,%3};"
        : "+f"(d[0]), "+f"(d[1]), "+f"(d[2]), "+f"(d[3])
        : "r"(a[0]), "r"(a[1]), "r"(a[2]), "r"(a[3]), "r"(b[0]), "r"(b[1]));
}
__device__ __forceinline__ uint32_t packbf2(float x, float y) {
    __nv_bfloat162 h = __floats2bfloat162_rn(x, y);
    return *(uint32_t*)&h;
}
__device__ __forceinline__ uint32_t packbf16pair(__nv_bfloat16 a, __nv_bfloat16 b) {
    return (uint32_t)__bfloat16_as_ushort(a) | ((uint32_t)__bfloat16_as_ushort(b) << 16);
}
// fast exp on fma pipe: exp(x)=2^(x*log2e), deg-5 poly, rel err ~2e-6, x<=~0
__device__ __forceinline__ float fexp(float x) {
    float y = x * 1.4426950408889634f;
    y = fmaxf(y, -126.0f);
    float t = y + 12582912.0f;                    // RN to integer in mantissa
    int   n = __float_as_int(t) - 0x4B400000;
    float f = y - (t - 12582912.0f);              // f in [-0.5, 0.5]
    float p = 1.3333558146428443e-3f;
    p = fmaf(p, f, 9.6181291076284772e-3f);
    p = fmaf(p, f, 5.5504108664821580e-2f);
    p = fmaf(p, f, 2.4022650695910072e-1f);
    p = fmaf(p, f, 6.9314718055994531e-1f);
    p = fmaf(p, f, 1.0f);
    return __int_as_float(__float_as_int(p) + (n << 23));
}

// ---------------- weight prep: W[K][N] fp32 -> T[N][K] bf16 hi/lo ----------------
__global__ void prep_w(const float* __restrict__ W, __nv_bfloat16* __restrict__ Thi,
                       __nv_bfloat16* __restrict__ Tlo, int K, int N)
{
    __shared__ float t[32][33];
    const int k0 = blockIdx.y * 32, n0 = blockIdx.x * 32;
    const int tx = threadIdx.x, ty = threadIdx.y;
#pragma unroll
    for (int r = 0; r < 4; r++)
        t[ty + 8*r][tx] = W[(size_t)(k0 + ty + 8*r) * N + n0 + tx];
    __syncthreads();
#pragma unroll
    for (int r = 0; r < 4; r++) {
        const int n = n0 + ty + 8*r, k = k0 + tx;
        float x = t[tx][ty + 8*r];
        __nv_bfloat16 hi = __float2bfloat16(x);
        __nv_bfloat16 lo = __float2bfloat16(x - __bfloat162float(hi));
        Thi[(size_t)n * K + k] = hi;
        Tlo[(size_t)n * K + k] = lo;
    }
}

// ---------------- bf16x3 mma.sync GEMM (unchanged, proven) ----------------
#define GS_BUF   40960
#define GS_AH    0
#define GS_AL    10240
#define GS_BH    20480
#define GS_BL    30720
#define SMEM_G   (2*GS_BUF)

template<int EPI>
__global__ __launch_bounds__(256, 1)
void bf16_gemm(const float* __restrict__ A,
               const __nv_bfloat16* __restrict__ Bhi, const __nv_bfloat16* __restrict__ Blo,
               float* __restrict__ C, const float* __restrict__ bias,
               const float* __restrict__ res, int N, int K,
               __nv_bfloat16* __restrict__ Ohi, __nv_bfloat16* __restrict__ Olo)
{
    extern __shared__ char smem[];
    const uint32_t sbase = smem_u32(smem);
    const int tid = threadIdx.x, wid = tid >> 5, lane = tid & 31;
    const int g = lane >> 2, t = lane & 3;
    const int wm = wid >> 2, wn = wid & 3;
    const int bm = blockIdx.y, bn = blockIdx.x;

    float c[4][4][4];
#pragma unroll
    for (int mt = 0; mt < 4; mt++)
#pragma unroll
        for (int nt = 0; nt < 4; nt++)
#pragma unroll
            for (int f = 0; f < 4; f++) c[mt][nt][f] = 0.f;

    const int arow = tid >> 1, ahalf = tid & 1;
    const float* gA = A + (size_t)(bm * 128 + arow) * K + ahalf * 16;

    auto cp_B = [&](int buf, int kb) {
#pragma unroll
        for (int j = 0; j < 4; j++) {
            const int cidx = tid + 256 * j;
            const int isLo = cidx >> 9;
            const int row  = (cidx >> 2) & 127;
            const int kc   = cidx & 3;
            const __nv_bfloat16* src = (isLo ? Blo : Bhi)
                + (size_t)(bn * 128 + row) * K + kb * 32 + kc * 8;
            const uint32_t dst = sbase + buf * GS_BUF + (isLo ? GS_BL : GS_BH)
                + row * 80 + kc * 16;
            asm volatile("cp.async.cg.shared.global [%0], [%1], 16;\n" :: "r"(dst), "l"(src));
        }
        asm volatile("cp.async.commit_group;\n");
    };

    float4 areg[4];
    auto load_A = [&](int kb) {
        const float* p = gA + kb * 32;
#pragma unroll
        for (int i = 0; i < 4; i++) areg[i] = *(const float4*)(p + 4 * i);
    };
    auto store_A = [&](int buf) {
        char* base = smem + buf * GS_BUF;
        const int off = arow * 80 + ahalf * 32;
        uint32_t* ph = (uint32_t*)(base + GS_AH + off);
        uint32_t* pl = (uint32_t*)(base + GS_AL + off);
#pragma unroll
        for (int i = 0; i < 4; i++) {
            float f0 = areg[i].x, f1 = areg[i].y, f2 = areg[i].z, f3 = areg[i].w;
            __nv_bfloat16 h0 = __float2bfloat16(f0), h1 = __float2bfloat16(f1);
            __nv_bfloat16 h2 = __float2bfloat16(f2), h3 = __float2bfloat16(f3);
            float l0 = f0 - __bfloat162float(h0), l1 = f1 - __bfloat162float(h1);
            float l2 = f2 - __bfloat162float(h2), l3 = f3 - __bfloat162float(h3);
            ph[2*i]   = packbf16pair(h0, h1);
            ph[2*i+1] = packbf16pair(h2, h3);
            pl[2*i]   = packbf2(l0, l1);
            pl[2*i+1] = packbf2(l2, l3);
        }
    };

    const uint32_t a_off = (uint32_t)((wm * 64 + (lane & 15)) * 80 + ((lane >> 4) << 4));
    const uint32_t b_off = (uint32_t)((wn * 32 + ((lane >> 4) << 3) + (lane & 7)) * 80
                                      + (((lane >> 3) & 1) << 4));

    const int niter = K >> 5;
    load_A(0);
    cp_B(0, 0);
    store_A(0);
    asm volatile("cp.async.wait_group 0;\n");
    __syncthreads();

    for (int it = 0; it < niter; it++) {
        const int buf = it & 1;
        if (it + 1 < niter) { load_A(it + 1); cp_B(buf ^ 1, it + 1); }

        const uint32_t sb = sbase + buf * GS_BUF;
#pragma unroll
        for (int ks = 0; ks < 2; ks++) {
            uint32_t Ah[4][4], Al[4][4], Bh[2][4], Bl[2][4];
#pragma unroll
            for (int mt = 0; mt < 4; mt++) {
                const uint32_t aa = sb + a_off + mt * (16 * 80) + ks * 32;
                ldsm4(Ah[mt], aa + GS_AH);
                ldsm4(Al[mt], aa + GS_AL);
            }
#pragma unroll
            for (int ng = 0; ng < 2; ng++) {
                const uint32_t ba = sb + b_off + ng * (16 * 80) + ks * 32;
                ldsm4(Bh[ng], ba + GS_BH);
                ldsm4(Bl[ng], ba + GS_BL);
            }
#pragma unroll
            for (int mt = 0; mt < 4; mt++)
#pragma unroll
                for (int nt = 0; nt < 4; nt++) {
                    const uint32_t* bh = &Bh[nt >> 1][(nt & 1) * 2];
                    const uint32_t* bl = &Bl[nt >> 1][(nt & 1) * 2];
                    mma_bf16(c[mt][nt], Ah[mt], bh);
                    mma_bf16(c[mt][nt], Ah[mt], bl);
                    mma_bf16(c[mt][nt], Al[mt], bh);
                }
        }

        if (it + 1 < niter) {
            store_A(buf ^ 1);
            asm volatile("cp.async.wait_group 0;\n");
        }
        __syncthreads();
    }

#pragma unroll
    for (int mt = 0; mt < 4; mt++) {
        const int r0 = bm * 128 + wm * 64 + mt * 16 + g;
#pragma unroll
        for (int nt = 0; nt < 4; nt++) {
            const int c0 = bn * 128 + wn * 32 + nt * 8 + t * 2;
#pragma unroll
            for (int half = 0; half < 2; half++) {
                const int r = r0 + half * 8;
                if (EPI == 1) {
                    float v0 = c[mt][nt][half * 2], v1 = c[mt][nt][half * 2 + 1];
                    const int which = c0 >> 10, cm = c0 & 1023;
                    if (which == 0) { v0 *= 0.125f; v1 *= 0.125f; }
                    __nv_bfloat16 h0 = __float2bfloat16(v0), h1 = __float2bfloat16(v1);
                    __nv_bfloat16 l0 = __float2bfloat16(v0 - __bfloat162float(h0));
                    __nv_bfloat16 l1 = __float2bfloat16(v1 - __bfloat162float(h1));
                    const size_t idx = (size_t)which * (NTOK * D_MODEL)
                        + (((size_t)((r >> 11) * NHEADS + (cm >> 6)) * SEQ + (r & 2047)) * DK + (cm & 63));
                    *(uint32_t*)(Ohi + idx) = packbf16pair(h0, h1);
                    *(uint32_t*)(Olo + idx) = packbf16pair(l0, l1);
                } else {
#pragma unroll
                    for (int e = 0; e < 2; e++) {
                        const int cc = c0 + e;
                        const float vacc = c[mt][nt][half * 2 + e];
                        if (EPI == 2) {
                            C[(size_t)r * N + cc] = vacc + bias[cc] + res[(size_t)r * N + cc];
                        } else {
                            float v = vacc + bias[cc];
                            C[(size_t)r * N + cc] = v > 0.f ? v : 0.f;
                        }
                    }
                }
            }
        }
    }
}

// ---------------- FA2-style tensor-core attention ----------------
// 128 q per CTA; warp w owns q rows [16w,16w+16). kv tile 64, double-buffered cp.async.
// All softmax state in registers (rows live entirely within one warp).
#define AQ_H   0            // Q hi: 128 rows x 144B = 18432
#define AQ_L   18432
#define AKV    36864        // per buffer: Kh,Kl,Vh,Vl each 64x144 = 9216 -> 36864/buffer
#define AKVBUF 36864
#define ATSMEM (36864 + 2*36864)   // 110592

__global__ __launch_bounds__(256, 2)
void attn_mma(const __nv_bfloat16* __restrict__ qkvh, const __nv_bfloat16* __restrict__ qkvl,
              const int* __restrict__ mask, float* __restrict__ ctx)
{
    extern __shared__ char sm[];
    const uint32_t sb = smem_u32(sm);
    const int tid = threadIdx.x, w = tid >> 5, lane = tid & 31;
    const int g = lane >> 2, t = lane & 3;
    const int qb = blockIdx.x, h = blockIdx.y, b = blockIdx.z;
    const size_t hoff = ((size_t)(b * NHEADS + h)) * SEQ * DK;

    const __nv_bfloat16* qh = qkvh + hoff + (size_t)qb * 128 * DK;
    const __nv_bfloat16* ql = qkvl + hoff + (size_t)qb * 128 * DK;
    const __nv_bfloat16* kh = qkvh + (size_t)NTOK * D_MODEL + hoff;
    const __nv_bfloat16* kl = qkvl + (size_t)NTOK * D_MODEL + hoff;
    const __nv_bfloat16* vh = qkvh + (size_t)2 * NTOK * D_MODEL + hoff;
    const __nv_bfloat16* vl = qkvl + (size_t)2 * NTOK * D_MODEL + hoff;

    // stage Q (plain stores)
#pragma unroll
    for (int j = 0; j < 8; j++) {
        const int cidx = tid + j * 256;
        const int arr = cidx >> 10, cc = cidx & 1023;
        const int row = cc >> 3, k8 = cc & 7;
        const __nv_bfloat16* src = (arr == 0 ? qh : ql) + row * DK + k8 * 8;
        *(uint4*)(sm + AQ_H + arr * 18432 + row * 144 + k8 * 16) = *(const uint4*)src;
    }

    auto prefetch_kv = [&](int buf, int kv0) {
#pragma unroll
        for (int j = 0; j < 8; j++) {
            const int cidx = tid + j * 256;
            const int arr = cidx >> 9, cc = cidx & 511;
            const int row = cc >> 3, k8 = cc & 7;
            const __nv_bfloat16* src =
                (arr == 0 ? kh : arr == 1 ? kl : arr == 2 ? vh : vl)
                + (size_t)(kv0 + row) * DK + k8 * 8;
            const uint32_t dst = sb + AKV + buf * AKVBUF + arr * 9216 + row * 144 + k8 * 16;
            asm volatile("cp.async.cg.shared.global [%0], [%1], 16;\n" :: "r"(dst), "l"(src));
        }
        asm volatile("cp.async.commit_group;\n");
    };

    prefetch_kv(0, 0);

    float m0 = -1e30f, m1 = -1e30f, l0 = 0.f, l1 = 0.f;
    float co[8][4];
#pragma unroll
    for (int nt = 0; nt < 8; nt++)
#pragma unroll
        for (int f = 0; f < 4; f++) co[nt][f] = 0.f;

    const uint32_t qa_off = (uint32_t)((w * 16 + (lane & 15)) * 144 + ((lane >> 4) << 4));
    const uint32_t kb_sub = (uint32_t)((((lane >> 4) << 3) + (lane & 7)) * 144
                                       + (((lane >> 3) & 1) << 4));
    const uint32_t vb_sub = (uint32_t)(((((lane >> 3) & 1) << 3) + (lane & 7)) * 144
                                       + ((lane >> 4) << 4));
    const int* mrow_base = mask + b * SEQ;

    for (int it = 0; it < SEQ / 64; it++) {
        const int buf = it & 1;
        const int kv0 = it * 64;
        asm volatile("cp.async.wait_group 0;\n");
        __syncthreads();                       // buffer ready; all warps past previous reads
        if (it + 1 < SEQ / 64) prefetch_kv(buf ^ 1, kv0 + 64);

        const uint32_t kvb = sb + AKV + buf * AKVBUF;

        // ---- S = Q K^T (bf16x3), per-warp m16 x n64 ----
        float cs[8][4];
#pragma unroll
        for (int nt = 0; nt < 8; nt++)
#pragma unroll
            for (int f = 0; f < 4; f++) cs[nt][f] = 0.f;
#pragma unroll
        for (int ks = 0; ks < 4; ks++) {
            uint32_t Qh_[4], Ql_[4];
            const uint32_t aa = sb + qa_off + ks * 32;
            ldsm4(Qh_, aa + AQ_H);
            ldsm4(Ql_, aa + AQ_L);
#pragma unroll
            for (int ng = 0; ng < 4; ng++) {
                uint32_t Kh_[4], Kl_[4];
                const uint32_t ba = kvb + ng * (16 * 144) + kb_sub + ks * 32;
                ldsm4(Kh_, ba);
                ldsm4(Kl_, ba + 9216);
#pragma unroll
                for (int h2 = 0; h2 < 2; h2++) {
                    const int nt = ng * 2 + h2;
                    mma_bf16(cs[nt], Qh_, &Kh_[h2 * 2]);
                    mma_bf16(cs[nt], Qh_, &Kl_[h2 * 2]);
                    mma_bf16(cs[nt], Ql_, &Kh_[h2 * 2]);
                }
            }
        }

        // ---- mask + in-register online softmax (rows g, g+8 within quad t) ----
#pragma unroll
        for (int nt = 0; nt < 8; nt++) {
            int2 mv = *(const int2*)(mrow_base + kv0 + nt * 8 + t * 2);
            if (mv.x == 0) { cs[nt][0] = -1e9f; cs[nt][2] = -1e9f; }
            if (mv.y == 0) { cs[nt][1] = -1e9f; cs[nt][3] = -1e9f; }
        }
        float mx0 = cs[0][0], mx1 = cs[0][2];
#pragma unroll
        for (int nt = 0; nt < 8; nt++) {
            mx0 = fmaxf(mx0, fmaxf(cs[nt][0], cs[nt][1]));
            mx1 = fmaxf(mx1, fmaxf(cs[nt][2], cs[nt][3]));
        }
        mx0 = fmaxf(mx0, __shfl_xor_sync(0xffffffffu, mx0, 1));
        mx0 = fmaxf(mx0, __shfl_xor_sync(0xffffffffu, mx0, 2));
        mx1 = fmaxf(mx1, __shfl_xor_sync(0xffffffffu, mx1, 1));
        mx1 = fmaxf(mx1, __shfl_xor_sync(0xffffffffu, mx1, 2));
        const float mn0 = fmaxf(m0, mx0), mn1 = fmaxf(m1, mx1);
        const float f0 = fexp(m0 - mn0), f1 = fexp(m1 - mn1);
        m0 = mn0; m1 = mn1;

        uint32_t phg[8], phg8[8], plg[8], plg8[8];
        float rs0 = 0.f, rs1 = 0.f;
#pragma unroll
        for (int nt = 0; nt < 8; nt++) {
            float p0 = fexp(cs[nt][0] - mn0);
            float p1 = fexp(cs[nt][1] - mn0);
            float p2 = fexp(cs[nt][2] - mn1);
            float p3 = fexp(cs[nt][3] - mn1);
            rs0 += p0 + p1; rs1 += p2 + p3;
            __nv_bfloat16 h0 = __float2bfloat16(p0), h1 = __float2bfloat16(p1);
            __nv_bfloat16 h2 = __float2bfloat16(p2), h3 = __float2bfloat16(p3);
            phg[nt]  = packbf16pair(h0, h1);
            phg8[nt] = packbf16pair(h2, h3);
            plg[nt]  = packbf2(p0 - __bfloat162float(h0), p1 - __bfloat162float(h1));
            plg8[nt] = packbf2(p2 - __bfloat162float(h2), p3 - __bfloat162float(h3));
        }
        rs0 += __shfl_xor_sync(0xffffffffu, rs0, 1);
        rs0 += __shfl_xor_sync(0xffffffffu, rs0, 2);
        rs1 += __shfl_xor_sync(0xffffffffu, rs1, 1);
        rs1 += __shfl_xor_sync(0xffffffffu, rs1, 2);
        l0 = l0 * f0 + rs0;
        l1 = l1 * f1 + rs1;

        // rescale O
#pragma unroll
        for (int nt = 0; nt < 8; nt++) {
            co[nt][0] *= f0; co[nt][1] *= f0;
            co[nt][2] *= f1; co[nt][3] *= f1;
        }

        // ---- O += P V (bf16x3); P a-frags straight from registers ----
#pragma unroll
        for (int kc = 0; kc < 4; kc++) {
            uint32_t Ah[4] = { phg[2*kc], phg8[2*kc], phg[2*kc+1], phg8[2*kc+1] };
            uint32_t Al[4] = { plg[2*kc], plg8[2*kc], plg[2*kc+1], plg8[2*kc+1] };
#pragma unroll
            for (int ng = 0; ng < 4; ng++) {
                uint32_t Vh_[4], Vl_[4];
                const uint32_t va = kvb + 18432 + kc * (16 * 144) + vb_sub + ng * 32;
                ldsm4t(Vh_, va);
                ldsm4t(Vl_, va + 9216);
#pragma unroll
                for (int h2 = 0; h2 < 2; h2++) {
                    const int nt = ng * 2 + h2;
                    mma_bf16(co[nt], Ah, &Vh_[h2 * 2]);
                    mma_bf16(co[nt], Ah, &Vl_[h2 * 2]);
                    mma_bf16(co[nt], Al, &Vh_[h2 * 2]);
                }
            }
        }
    }

    const float inv0 = 1.0f / l0, inv1 = 1.0f / l1;
    const int r0 = qb * 128 + w * 16 + g;
    float* dst0 = ctx + ((size_t)(b * SEQ + r0)) * D_MODEL + h * 64;
    float* dst1 = ctx + ((size_t)(b * SEQ + r0 + 8)) * D_MODEL + h * 64;
#pragma unroll
    for (int nt = 0; nt < 8; nt++) {
        const int col = nt * 8 + t * 2;
        *(float2*)(dst0 + col) = make_float2(co[nt][0] * inv0, co[nt][1] * inv0);
        *(float2*)(dst1 + col) = make_float2(co[nt][2] * inv1, co[nt][3] * inv1);
    }
}

// ---------------- LayerNorm (ddof=1, eps added to std) ----------------
__device__ __forceinline__ float warp_sum(float s) {
#pragma unroll
    for (int off = 16; off; off >>= 1) s += __shfl_xor_sync(0xffffffffu, s, off);
    return s;
}

__global__ __launch_bounds__(256)
void ln_kernel(const float* __restrict__ in, const float* __restrict__ alpha,
               const float* __restrict__ beta, float* __restrict__ out)
{
    __shared__ float red[8];
    const int row = blockIdx.x, tid = threadIdx.x;
    const float* rp = in + (size_t)row * D_MODEL;
    float4 v = *(const float4*)(rp + tid*4);

    float s = v.x + v.y + v.z + v.w;
    s = warp_sum(s);
    if ((tid & 31) == 0) red[tid >> 5] = s;
    __syncthreads();
    float tot = 0.f;
#pragma unroll
    for (int i = 0; i < 8; i++) tot += red[i];
    float mean = tot * (1.0f / 1024.0f);

    float dx = v.x - mean, dy = v.y - mean, dz = v.z - mean, dw = v.w - mean;
    float sq = dx*dx + dy*dy + dz*dz + dw*dw;
    __syncthreads();
    sq = warp_sum(sq);
    if ((tid & 31) == 0) red[tid >> 5] = sq;
    __syncthreads();
    float tot2 = 0.f;
#pragma unroll
    for (int i = 0; i < 8; i++) tot2 += red[i];
    float var  = tot2 * (1.0f / 1023.0f);
    float rstd = 1.0f / (sqrtf(var) + 1e-6f);

    float4 a = *(const float4*)(alpha + tid*4);
    float4 bb = *(const float4*)(beta + tid*4);
    float4 o;
    o.x = a.x * dx * rstd + bb.x;
    o.y = a.y * dy * rstd + bb.y;
    o.z = a.z * dz * rstd + bb.z;
    o.w = a.w * dw * rstd + bb.w;
    *(float4*)(out + (size_t)row * D_MODEL + tid*4) = o;
}

// ---------------- host ----------------
extern "C" void kernel_launch(void* const* d_in, const int* in_sizes, int n_in,
                              void* d_out, int out_size)
{
    const float* x      = (const float*)d_in[0];
    const int*   mask   = (const int*)  d_in[1];
    const float* wq     = (const float*)d_in[2];
    const float* wk     = (const float*)d_in[3];
    const float* wv     = (const float*)d_in[4];
    const float* wo     = (const float*)d_in[5];
    const float* wo_b   = (const float*)d_in[6];
    const float* w1     = (const float*)d_in[7];
    const float* b1     = (const float*)d_in[8];
    const float* w2     = (const float*)d_in[9];
    const float* b2     = (const float*)d_in[10];
    const float* alpha1 = (const float*)d_in[11];
    const float* bias1  = (const float*)d_in[12];
    const float* alpha2 = (const float*)d_in[13];
    const float* bias2  = (const float*)d_in[14];
    float* out = (float*)d_out;

    float *ctx, *s1, *x1, *ff, *s2;
    __nv_bfloat16 *qkvh, *qkvl;
    __nv_bfloat16 *wqkv_hi, *wqkv_lo, *wo_hi, *wo_lo, *w1_hi, *w1_lo, *w2_hi, *w2_lo;
    cudaGetSymbolAddress((void**)&ctx, g_ctx);
    cudaGetSymbolAddress((void**)&s1,  g_s1);
    cudaGetSymbolAddress((void**)&x1,  g_x1);
    cudaGetSymbolAddress((void**)&ff,  g_ff);
    cudaGetSymbolAddress((void**)&s2,  g_s2);
    cudaGetSymbolAddress((void**)&qkvh, g_qkvh);
    cudaGetSymbolAddress((void**)&qkvl, g_qkvl);
    cudaGetSymbolAddress((void**)&wqkv_hi, g_wqkv_hi);
    cudaGetSymbolAddress((void**)&wqkv_lo, g_wqkv_lo);
    cudaGetSymbolAddress((void**)&wo_hi, g_wo_hi);
    cudaGetSymbolAddress((void**)&wo_lo, g_wo_lo);
    cudaGetSymbolAddress((void**)&w1_hi, g_w1_hi);
    cudaGetSymbolAddress((void**)&w1_lo, g_w1_lo);
    cudaGetSymbolAddress((void**)&w2_hi, g_w2_hi);
    cudaGetSymbolAddress((void**)&w2_lo, g_w2_lo);

    // idempotent; no static guards allowed
    cudaFuncSetAttribute(bf16_gemm<1>, cudaFuncAttributeMaxDynamicSharedMemorySize, SMEM_G);
    cudaFuncSetAttribute(bf16_gemm<2>, cudaFuncAttributeMaxDynamicSharedMemorySize, SMEM_G);
    cudaFuncSetAttribute(bf16_gemm<3>, cudaFuncAttributeMaxDynamicSharedMemorySize, SMEM_G);
    cudaFuncSetAttribute(attn_mma,     cudaFuncAttributeMaxDynamicSharedMemorySize, ATSMEM);

    dim3 tblk(32, 8);
    prep_w<<<dim3(D_MODEL/32, D_MODEL/32), tblk>>>(wq, wqkv_hi,                     wqkv_lo,                     D_MODEL, D_MODEL);
    prep_w<<<dim3(D_MODEL/32, D_MODEL/32), tblk>>>(wk, wqkv_hi + D_MODEL*D_MODEL,   wqkv_lo + D_MODEL*D_MODEL,   D_MODEL, D_MODEL);
    prep_w<<<dim3(D_MODEL/32, D_MODEL/32), tblk>>>(wv, wqkv_hi + 2*D_MODEL*D_MODEL, wqkv_lo + 2*D_MODEL*D_MODEL, D_MODEL, D_MODEL);
    prep_w<<<dim3(D_MODEL/32, D_MODEL/32), tblk>>>(wo, wo_hi, wo_lo, D_MODEL, D_MODEL);
    prep_w<<<dim3(DFF/32,     D_MODEL/32), tblk>>>(w1, w1_hi, w1_lo, D_MODEL, DFF);
    prep_w<<<dim3(D_MODEL/32, DFF/32),     tblk>>>(w2, w2_hi, w2_lo, DFF, D_MODEL);

    // fused QKV projection (N=3072) -> bf16 hi/lo head-transposed, q pre-scaled
    bf16_gemm<1><<<dim3(24, 32), 256, SMEM_G>>>(x, wqkv_hi, wqkv_lo, nullptr, nullptr, nullptr,
                                                3*D_MODEL, D_MODEL, qkvh, qkvl);

    attn_mma<<<dim3(SEQ/128, NHEADS, BATCH), 256, ATSMEM>>>(qkvh, qkvl, mask, ctx);

    // O projection + residual, LN1
    bf16_gemm<2><<<dim3(8, 32), 256, SMEM_G>>>(ctx, wo_hi, wo_lo, s1, wo_b, x, D_MODEL, D_MODEL, nullptr, nullptr);
    ln_kernel<<<NTOK, 256>>>(s1, alpha1, bias1, x1);

    // FFN
    bf16_gemm<3><<<dim3(32, 32), 256, SMEM_G>>>(x1, w1_hi, w1_lo, ff, b1, nullptr, DFF, D_MODEL, nullptr, nullptr);
    bf16_gemm<2><<<dim3(8, 32), 256, SMEM_G>>>(ff, w2_hi, w2_lo, s2, b2, x1, D_MODEL, DFF, nullptr, nullptr);
    ln_kernel<<<NTOK, 256>>>(s2, alpha2, bias2, out);
}